// round 5
// baseline (speedup 1.0000x reference)
#include <cuda_runtime.h>
#include <math.h>
#include <cub/cub.cuh>

#define BB 4
#define CC 64
#define NN 4096
#define INTER 16
#define TILE 256
#define NT (NN / TILE)   // 16

// ---------------- scratch (device globals; no allocations allowed) ----------
__device__ double g_wa[CC], g_wd[CC];
__device__ double g_ca, g_cd;
__device__ __align__(16) float g_WvgT[CC * CC];   // [cin][o]
__device__ float g_bvg[CC];
__device__ float g_a[BB * NN];
__device__ double g_dd[BB * NN];                    // double-precision d
__device__ __align__(16) float g_vp[BB * NN * CC];  // [b][n][c]
__device__ __align__(16) float g_vs[BB * NN * CC];  // v permuted into sorted order [b][r][c]
__device__ float g_s[BB * NN];                       // sorted a (ascending)
__device__ float g_e[BB * NN];                       // expf(sorted a)
__device__ int   g_idx[BB * NN];                     // permutation
__device__ double g_tsum[BB * NT * CC * 3];          // tile sums -> exclusive offsets
__device__ __align__(16) float g_Pva[BB * (NN + 1) * CC];  // prefix of v*a, [b][r][c]
__device__ __align__(16) float g_Pv [BB * (NN + 1) * CC];  // prefix of v
__device__ __align__(16) float g_Pve[BB * (NN + 1) * CC];  // prefix of v*exp(a)
__device__ double g_Pa[BB * (NN + 1)];               // prefix of a (double)
__device__ double g_Pe[BB * (NN + 1)];               // prefix of exp(a) (double)

// ---------------- K1: fold weights (double for the a/d path) -------------
__global__ void k1_precompute(const float* __restrict__ Wq, const float* __restrict__ bq,
                              const float* __restrict__ Wk, const float* __restrict__ bk,
                              const float* __restrict__ wcq, const float* __restrict__ wck,
                              const float* __restrict__ Wv, const float* __restrict__ bv,
                              const float* __restrict__ Wg) {
    int t = threadIdx.x;  // 256
    if (t < CC) {
        double sa = 0.0, sd = 0.0;
        for (int i = 0; i < INTER; i++) {
            sa += (double)wcq[i] * (double)Wq[i * CC + t];
            sd += (double)wck[i] * (double)Wk[i * CC + t];
        }
        g_wa[t] = sa;
        g_wd[t] = sd;
    }
    if (t >= 64 && t < 128) {
        int o = t - 64;
        float s = 0.f;
        for (int m = 0; m < CC; m++) s += Wg[o * CC + m] * bv[m];
        g_bvg[o] = s;
    }
    if (t == 128) {
        double ca = 0.0, cd = 0.0;
        for (int i = 0; i < INTER; i++) {
            ca += (double)wcq[i] * (double)bq[i];
            cd += (double)wck[i] * (double)bk[i];
        }
        g_ca = ca;
        g_cd = cd;
    }
    for (int e = t; e < CC * CC; e += 256) {
        int cin = e / CC, o = e % CC;
        float s = 0.f;
        for (int m = 0; m < CC; m++) s += Wg[o * CC + m] * Wv[m * CC + cin];
        g_WvgT[cin * CC + o] = s;
    }
}

// ---------------- K2: per-pixel projections a, d, v' ---------------------
__global__ void k2_proj(const float* __restrict__ x) {
    __shared__ __align__(16) float shW[CC * CC];
    __shared__ double shwa[CC], shwd[CC];
    __shared__ float shb[CC];
    int tid = threadIdx.x;  // 128
    for (int e = tid; e < CC * CC; e += 128) shW[e] = g_WvgT[e];
    if (tid < CC) { shwa[tid] = g_wa[tid]; shwd[tid] = g_wd[tid]; shb[tid] = g_bvg[tid]; }
    __syncthreads();

    int g = blockIdx.x * 128 + tid;  // 0 .. B*N-1
    int b = g / NN, n = g % NN;
    const float* xb = x + (size_t)b * CC * NN + n;

    float acc[CC];
#pragma unroll
    for (int o = 0; o < CC; o++) acc[o] = shb[o];
    double aa = g_ca, dd = g_cd;

    for (int cin = 0; cin < CC; cin++) {
        float xv = xb[(size_t)cin * NN];
        aa += shwa[cin] * (double)xv;
        dd += shwd[cin] * (double)xv;
        const float4* wrow = (const float4*)&shW[cin * CC];
#pragma unroll
        for (int o4 = 0; o4 < CC / 4; o4++) {
            float4 w = wrow[o4];
            acc[o4 * 4 + 0] += w.x * xv;
            acc[o4 * 4 + 1] += w.y * xv;
            acc[o4 * 4 + 2] += w.z * xv;
            acc[o4 * 4 + 3] += w.w * xv;
        }
    }
    g_a[g] = (float)aa;
    g_dd[g] = dd;
    float4* vout = (float4*)&g_vp[(size_t)g * CC];
#pragma unroll
    for (int o4 = 0; o4 < CC / 4; o4++)
        vout[o4] = make_float4(acc[o4 * 4 + 0], acc[o4 * 4 + 1], acc[o4 * 4 + 2], acc[o4 * 4 + 3]);
}

// ---------------- K3: per-batch radix sort + permute v + exp -------------
__global__ void __launch_bounds__(1024) k3_sort() {
    typedef cub::BlockRadixSort<float, 1024, 4, int> Sorter;
    __shared__ typename Sorter::TempStorage tmp;
    int b = blockIdx.x;
    int tid = threadIdx.x;  // 1024

    float keys[4];
    int vals[4];
#pragma unroll
    for (int u = 0; u < 4; u++) {
        int r = 4 * tid + u;
        keys[u] = g_a[b * NN + r];
        vals[u] = r;
    }
    Sorter(tmp).Sort(keys, vals);  // ascending, blocked output
#pragma unroll
    for (int u = 0; u < 4; u++) {
        int r = 4 * tid + u;
        g_s[b * NN + r]   = keys[u];
        g_idx[b * NN + r] = vals[u];
        g_e[b * NN + r]   = expf(keys[u]);
    }
    __syncthreads();

    // permute v into sorted order: g_vs[b][r][c] = g_vp[b][idx[r]][c]
    const float4* vin = (const float4*)g_vp;
    float4* vout = (float4*)g_vs;
    for (int e = tid; e < NN * (CC / 4); e += 1024) {
        int row = e >> 4;        // rank
        int p = e & 15;          // float4 chunk within row
        int src = g_idx[b * NN + row];
        vout[((size_t)(b * NN + row) * CC) / 4 + p] =
            vin[((size_t)(b * NN + src) * CC) / 4 + p];
    }
}

// ---------------- K4a: per-tile channel partial sums ----------------------
// grid = B*NT, block 256 = (c fast 64, q slow 4). Each (c,q) sums 64 ranks.
__global__ void k4a_tilesum() {
    __shared__ double sred[3 * 4 * CC];
    int blk = blockIdx.x;
    int b = blk / NT, tile = blk % NT;
    int tid = threadIdx.x;
    int c = tid & 63, q = tid >> 6;
    int rbase = tile * TILE + q * 64;

    const float* vs = &g_vs[((size_t)b * NN) * CC];
    const float* s  = &g_s[b * NN];
    const float* e  = &g_e[b * NN];

    double s0 = 0.0, s1 = 0.0, s2 = 0.0;
    for (int k = 0; k < 64; k++) {
        int r = rbase + k;
        double f = (double)vs[(size_t)r * CC + c];   // coalesced: lanes over c
        double av = (double)s[r];                    // broadcast
        double ev = (double)e[r];                    // broadcast
        s0 += f * av;
        s1 += f;
        s2 += f * ev;
    }
    sred[(0 * 4 + q) * CC + c] = s0;
    sred[(1 * 4 + q) * CC + c] = s1;
    sred[(2 * 4 + q) * CC + c] = s2;
    __syncthreads();
    if (tid < CC) {
        size_t out = ((size_t)(b * NT + tile) * CC + tid) * 3;
        for (int st = 0; st < 3; st++) {
            double t = sred[(st * 4 + 0) * CC + tid] + sred[(st * 4 + 1) * CC + tid]
                     + sred[(st * 4 + 2) * CC + tid] + sred[(st * 4 + 3) * CC + tid];
            g_tsum[out + st] = t;
        }
    }
}

// ---------------- K4b: tile-sum exclusive scan + scalar Pa/Pe scan --------
// grid = B, block 256.
__global__ void k4b_offsets() {
    __shared__ double sh0[256], sh1[256];
    int b = blockIdx.x;
    int tid = threadIdx.x;

    // exclusive scan of tile sums per (c, stream); also zero row 0 of P arrays
    if (tid < CC) {
        double run0 = 0.0, run1 = 0.0, run2 = 0.0;
        for (int t = 0; t < NT; t++) {
            size_t o = ((size_t)(b * NT + t) * CC + tid) * 3;
            double v0 = g_tsum[o + 0], v1 = g_tsum[o + 1], v2 = g_tsum[o + 2];
            g_tsum[o + 0] = run0; g_tsum[o + 1] = run1; g_tsum[o + 2] = run2;
            run0 += v0; run1 += v1; run2 += v2;
        }
        size_t base = ((size_t)b * (NN + 1)) * CC + tid;
        g_Pva[base] = 0.f; g_Pv[base] = 0.f; g_Pve[base] = 0.f;
    }

    // scalar streams: full-resolution Pa, Pe (fp64)
    int r0 = tid * 16;
    const float* s = &g_s[b * NN];
    const float* e = &g_e[b * NN];
    double l0 = 0.0, l1 = 0.0;
    for (int u = 0; u < 16; u++) {
        l0 += (double)s[r0 + u];
        l1 += (double)e[r0 + u];
    }
    sh0[tid] = l0; sh1[tid] = l1;
    __syncthreads();
    for (int off = 1; off < 256; off <<= 1) {
        double t0 = 0, t1 = 0;
        if (tid >= off) { t0 = sh0[tid - off]; t1 = sh1[tid - off]; }
        __syncthreads();
        sh0[tid] += t0; sh1[tid] += t1;
        __syncthreads();
    }
    double b0 = 0, b1 = 0;
    if (tid > 0) { b0 = sh0[tid - 1]; b1 = sh1[tid - 1]; }
    size_t base = (size_t)b * (NN + 1);
    if (tid == 0) { g_Pa[base] = 0.0; g_Pe[base] = 0.0; }
    double r0d = b0, r1d = b1;
    for (int u = 0; u < 16; u++) {
        int r = r0 + u;
        r0d += (double)s[r];
        r1d += (double)e[r];
        g_Pa[base + r + 1] = r0d;
        g_Pe[base + r + 1] = r1d;
    }
}

// ---------------- K4c: write full channel prefixes ------------------------
// grid = B*NT, block 256 = (c fast, q slow). Coalesced loads AND stores.
__global__ void k4c_scan() {
    __shared__ double pred[3 * 4 * CC];
    int blk = blockIdx.x;
    int b = blk / NT, tile = blk % NT;
    int tid = threadIdx.x;
    int c = tid & 63, q = tid >> 6;
    int rbase = tile * TILE + q * 64;

    const float* vs = &g_vs[((size_t)b * NN) * CC];
    const float* s  = &g_s[b * NN];
    const float* e  = &g_e[b * NN];

    // pass 1: own partial sums (for intra-tile q-offsets)
    double s0 = 0.0, s1 = 0.0, s2 = 0.0;
    for (int k = 0; k < 64; k++) {
        int r = rbase + k;
        double f = (double)vs[(size_t)r * CC + c];
        s0 += f * (double)s[r];
        s1 += f;
        s2 += f * (double)e[r];
    }
    pred[(0 * 4 + q) * CC + c] = s0;
    pred[(1 * 4 + q) * CC + c] = s1;
    pred[(2 * 4 + q) * CC + c] = s2;
    __syncthreads();

    size_t toff = ((size_t)(b * NT + tile) * CC + c) * 3;
    double r0d = g_tsum[toff + 0];
    double r1d = g_tsum[toff + 1];
    double r2d = g_tsum[toff + 2];
    for (int qq = 0; qq < 4; qq++) {
        if (qq < q) {
            r0d += pred[(0 * 4 + qq) * CC + c];
            r1d += pred[(1 * 4 + qq) * CC + c];
            r2d += pred[(2 * 4 + qq) * CC + c];
        }
    }

    // pass 2: sequential scan, coalesced stores (lanes over c, same r)
    size_t pbase = ((size_t)b * (NN + 1)) * CC + c;
    for (int k = 0; k < 64; k++) {
        int r = rbase + k;
        double f = (double)vs[(size_t)r * CC + c];
        r0d += f * (double)s[r];
        r1d += f;
        r2d += f * (double)e[r];
        size_t o = pbase + (size_t)(r + 1) * CC;
        g_Pva[o] = (float)r0d;
        g_Pv[o]  = (float)r1d;
        g_Pve[o] = (float)r2d;
    }
}

// ---------------- K5: per-column output ----------------------------------
__global__ void k5_out(const float* __restrict__ bg, float* __restrict__ out) {
    __shared__ float sh_s[NN];                       // 16KB
    __shared__ __align__(16) float sh_tva[CC], sh_tv[CC], sh_bg[CC];
    int blk = blockIdx.x;  // B*16
    int b = blk / 16;
    int jbase = (blk % 16) * 256;
    int tid = threadIdx.x;  // 256
    for (int e = tid; e < NN; e += 256) sh_s[e] = g_s[b * NN + e];
    if (tid < CC) {
        size_t totrow = ((size_t)b * (NN + 1) + NN) * CC;
        sh_tva[tid] = g_Pva[totrow + tid];
        sh_tv[tid]  = g_Pv[totrow + tid];
        sh_bg[tid]  = bg[tid];
    }
    __syncthreads();

    int j = jbase + tid;
    double djd = g_dd[b * NN + j];
    float dj = (float)djd;
    float t = (float)(-djd);
    // r = count of sorted a_i <= t  (exp branch set)
    int lo = 0, hi = NN;
    while (lo < hi) {
        int mid = (lo + hi) >> 1;
        if (sh_s[mid] <= t) lo = mid + 1; else hi = mid;
    }
    int r = lo;
    double edd = exp(djd);
    float ed = (float)edd;

    // S in full double precision (singular columns amplify any S error)
    size_t sbase = (size_t)b * (NN + 1);
    double SaN = g_Pa[sbase + NN];
    double S = (SaN - g_Pa[sbase + r]) + (double)(NN - r) * djd
             + edd * g_Pe[sbase + r] - (double)r;
    float inv = (float)(1.0 / (1.5 * S));

    size_t rowr4 = (((size_t)b * (NN + 1) + r) * CC) / 4;
    const float4* Pva4 = (const float4*)g_Pva;
    const float4* Pv4  = (const float4*)g_Pv;
    const float4* Pve4 = (const float4*)g_Pve;
    const float4* tva4 = (const float4*)sh_tva;
    const float4* tv4  = (const float4*)sh_tv;
    float* ob = out + (size_t)b * CC * NN + j;
#pragma unroll 4
    for (int c4 = 0; c4 < CC / 4; c4++) {
        float4 pva = Pva4[rowr4 + c4];
        float4 pv  = Pv4[rowr4 + c4];
        float4 pve = Pve4[rowr4 + c4];
        float4 tva = tva4[c4];
        float4 tv  = tv4[c4];
        int c = c4 * 4;
        ob[(size_t)(c + 0) * NN] = inv * ((tva.x - pva.x) + dj * (tv.x - pv.x) + ed * pve.x - pv.x) + sh_bg[c + 0];
        ob[(size_t)(c + 1) * NN] = inv * ((tva.y - pva.y) + dj * (tv.y - pv.y) + ed * pve.y - pv.y) + sh_bg[c + 1];
        ob[(size_t)(c + 2) * NN] = inv * ((tva.z - pva.z) + dj * (tv.z - pv.z) + ed * pve.z - pv.z) + sh_bg[c + 2];
        ob[(size_t)(c + 3) * NN] = inv * ((tva.w - pva.w) + dj * (tv.w - pv.w) + ed * pve.w - pv.w) + sh_bg[c + 3];
    }
}

// ---------------- launcher ----------------------------------------------
extern "C" void kernel_launch(void* const* d_in, const int* in_sizes, int n_in,
                              void* d_out, int out_size) {
    const float* x   = (const float*)d_in[0];
    const float* Wq  = (const float*)d_in[1];
    const float* bq  = (const float*)d_in[2];
    const float* Wk  = (const float*)d_in[3];
    const float* bk  = (const float*)d_in[4];
    const float* wcq = (const float*)d_in[5];
    const float* wck = (const float*)d_in[6];
    const float* Wv  = (const float*)d_in[7];
    const float* bv  = (const float*)d_in[8];
    const float* Wg  = (const float*)d_in[9];
    const float* bg  = (const float*)d_in[10];
    float* out = (float*)d_out;

    k1_precompute<<<1, 256>>>(Wq, bq, Wk, bk, wcq, wck, Wv, bv, Wg);
    k2_proj<<<(BB * NN) / 128, 128>>>(x);
    k3_sort<<<BB, 1024>>>();
    k4a_tilesum<<<BB * NT, 256>>>();
    k4b_offsets<<<BB, 256>>>();
    k4c_scan<<<BB * NT, 256>>>();
    k5_out<<<BB * 16, 256>>>(bg, out);
}

// round 6
// speedup vs baseline: 1.8896x; 1.8896x over previous
#include <cuda_runtime.h>
#include <math.h>
#include <cub/cub.cuh>

#define BB 4
#define CC 64
#define NN 4096
#define INTER 16
#define TILE 128
#define NT (NN / TILE)   // 32

// ---------------- scratch (device globals; no allocations allowed) ----------
__device__ double g_wa[CC], g_wd[CC];
__device__ double g_ca, g_cd;
__device__ __align__(16) float g_WvgT[CC * CC];   // [cin][o]
__device__ float g_bvg[CC];
__device__ float g_a[BB * NN];
__device__ double g_dd[BB * NN];                    // double-precision d
__device__ __align__(16) float g_vp[BB * NN * CC];  // [b][n][c]
__device__ __align__(16) float g_vs[BB * NN * CC];  // v permuted into sorted order [b][r][c]
__device__ float g_s[BB * NN];                       // sorted a (ascending)
__device__ float g_e[BB * NN];                       // expf(sorted a)
__device__ int   g_idx[BB * NN];                     // permutation
__device__ double g_tsum[BB * NT * CC * 3];          // tile sums -> exclusive offsets (fp64)
__device__ __align__(16) float g_Pva[BB * (NN + 1) * CC];  // prefix of v*a, [b][r][c]
__device__ __align__(16) float g_Pv [BB * (NN + 1) * CC];  // prefix of v
__device__ __align__(16) float g_Pve[BB * (NN + 1) * CC];  // prefix of v*exp(a)
__device__ double g_Pa[BB * (NN + 1)];               // prefix of a (double)
__device__ double g_Pe[BB * (NN + 1)];               // prefix of exp(a) (double)

// ---------------- K1: fold weights (double for the a/d path) -------------
__global__ void k1_precompute(const float* __restrict__ Wq, const float* __restrict__ bq,
                              const float* __restrict__ Wk, const float* __restrict__ bk,
                              const float* __restrict__ wcq, const float* __restrict__ wck,
                              const float* __restrict__ Wv, const float* __restrict__ bv,
                              const float* __restrict__ Wg) {
    int t = threadIdx.x;  // 256
    if (t < CC) {
        double sa = 0.0, sd = 0.0;
        for (int i = 0; i < INTER; i++) {
            sa += (double)wcq[i] * (double)Wq[i * CC + t];
            sd += (double)wck[i] * (double)Wk[i * CC + t];
        }
        g_wa[t] = sa;
        g_wd[t] = sd;
    }
    if (t >= 64 && t < 128) {
        int o = t - 64;
        float s = 0.f;
        for (int m = 0; m < CC; m++) s += Wg[o * CC + m] * bv[m];
        g_bvg[o] = s;
    }
    if (t == 128) {
        double ca = 0.0, cd = 0.0;
        for (int i = 0; i < INTER; i++) {
            ca += (double)wcq[i] * (double)bq[i];
            cd += (double)wck[i] * (double)bk[i];
        }
        g_ca = ca;
        g_cd = cd;
    }
    for (int e = t; e < CC * CC; e += 256) {
        int cin = e / CC, o = e % CC;
        float s = 0.f;
        for (int m = 0; m < CC; m++) s += Wg[o * CC + m] * Wv[m * CC + cin];
        g_WvgT[cin * CC + o] = s;
    }
}

// ---------------- K2: per-pixel projections a, d, v' ---------------------
__global__ void k2_proj(const float* __restrict__ x) {
    __shared__ __align__(16) float shW[CC * CC];
    __shared__ double shwa[CC], shwd[CC];
    __shared__ float shb[CC];
    int tid = threadIdx.x;  // 128
    for (int e = tid; e < CC * CC; e += 128) shW[e] = g_WvgT[e];
    if (tid < CC) { shwa[tid] = g_wa[tid]; shwd[tid] = g_wd[tid]; shb[tid] = g_bvg[tid]; }
    __syncthreads();

    int g = blockIdx.x * 128 + tid;  // 0 .. B*N-1
    int b = g / NN, n = g % NN;
    const float* xb = x + (size_t)b * CC * NN + n;

    float acc[CC];
#pragma unroll
    for (int o = 0; o < CC; o++) acc[o] = shb[o];
    double aa = g_ca, dd = g_cd;

    for (int cin = 0; cin < CC; cin++) {
        float xv = xb[(size_t)cin * NN];
        aa += shwa[cin] * (double)xv;
        dd += shwd[cin] * (double)xv;
        const float4* wrow = (const float4*)&shW[cin * CC];
#pragma unroll
        for (int o4 = 0; o4 < CC / 4; o4++) {
            float4 w = wrow[o4];
            acc[o4 * 4 + 0] += w.x * xv;
            acc[o4 * 4 + 1] += w.y * xv;
            acc[o4 * 4 + 2] += w.z * xv;
            acc[o4 * 4 + 3] += w.w * xv;
        }
    }
    g_a[g] = (float)aa;
    g_dd[g] = dd;
    float4* vout = (float4*)&g_vp[(size_t)g * CC];
#pragma unroll
    for (int o4 = 0; o4 < CC / 4; o4++)
        vout[o4] = make_float4(acc[o4 * 4 + 0], acc[o4 * 4 + 1], acc[o4 * 4 + 2], acc[o4 * 4 + 3]);
}

// ---------------- K3: per-batch radix sort of (a, idx) --------------------
__global__ void __launch_bounds__(512) k3_sort() {
    typedef cub::BlockRadixSort<float, 512, 8, int> Sorter;
    __shared__ typename Sorter::TempStorage tmp;
    int b = blockIdx.x;
    int tid = threadIdx.x;  // 512

    float keys[8];
    int vals[8];
#pragma unroll
    for (int u = 0; u < 8; u++) {
        int r = 8 * tid + u;
        keys[u] = g_a[b * NN + r];
        vals[u] = r;
    }
    Sorter(tmp).Sort(keys, vals);  // ascending, blocked output
#pragma unroll
    for (int u = 0; u < 8; u++) {
        int r = 8 * tid + u;
        g_s[b * NN + r]   = keys[u];
        g_idx[b * NN + r] = vals[u];
    }
}

// ---------------- K3p: permute v into sorted order + exp ------------------
// grid = BB*16, block 256. Each block: 256 ranks.
__global__ void k3p_permute() {
    int blk = blockIdx.x;
    int b = blk / 16, seg = blk % 16;
    int tid = threadIdx.x;
    int rbase = seg * 256;

    g_e[b * NN + rbase + tid] = expf(g_s[b * NN + rbase + tid]);

    const float4* vin = (const float4*)g_vp;
    float4* vout = (float4*)g_vs;
    for (int e = tid; e < 256 * (CC / 4); e += 256) {
        int row = rbase + (e >> 4);
        int p = e & 15;
        int src = g_idx[b * NN + row];
        vout[((size_t)(b * NN + row) * CC) / 4 + p] =
            vin[((size_t)(b * NN + src) * CC) / 4 + p];
    }
}

// ---------------- K4a: per-tile channel partial sums (fp32) ---------------
// grid = B*NT, block 256 = (c fast 64, q slow 4). Each (c,q) sums 32 ranks.
__global__ void k4a_tilesum() {
    __shared__ float sred[3 * 4 * CC];
    int blk = blockIdx.x;
    int b = blk / NT, tile = blk % NT;
    int tid = threadIdx.x;
    int c = tid & 63, q = tid >> 6;
    int rbase = tile * TILE + q * 32;

    const float* vs = &g_vs[((size_t)b * NN) * CC];
    const float* s  = &g_s[b * NN];
    const float* e  = &g_e[b * NN];

    float s0 = 0.f, s1 = 0.f, s2 = 0.f;
#pragma unroll 4
    for (int k = 0; k < 32; k++) {
        int r = rbase + k;
        float f = vs[(size_t)r * CC + c];   // coalesced: lanes over c
        s0 += f * s[r];
        s1 += f;
        s2 += f * e[r];
    }
    sred[(0 * 4 + q) * CC + c] = s0;
    sred[(1 * 4 + q) * CC + c] = s1;
    sred[(2 * 4 + q) * CC + c] = s2;
    __syncthreads();
    if (tid < CC) {
        size_t out = ((size_t)(b * NT + tile) * CC + tid) * 3;
        for (int st = 0; st < 3; st++) {
            float t = sred[(st * 4 + 0) * CC + tid] + sred[(st * 4 + 1) * CC + tid]
                    + sred[(st * 4 + 2) * CC + tid] + sred[(st * 4 + 3) * CC + tid];
            g_tsum[out + st] = (double)t;
        }
    }
}

// ---------------- K4b: tile-sum exclusive scan (fp64) + scalar Pa/Pe ------
// grid = B, block 256.
__global__ void k4b_offsets() {
    __shared__ double sh0[256], sh1[256];
    int b = blockIdx.x;
    int tid = threadIdx.x;

    if (tid < CC) {
        double run0 = 0.0, run1 = 0.0, run2 = 0.0;
        for (int t = 0; t < NT; t++) {
            size_t o = ((size_t)(b * NT + t) * CC + tid) * 3;
            double v0 = g_tsum[o + 0], v1 = g_tsum[o + 1], v2 = g_tsum[o + 2];
            g_tsum[o + 0] = run0; g_tsum[o + 1] = run1; g_tsum[o + 2] = run2;
            run0 += v0; run1 += v1; run2 += v2;
        }
        size_t base = ((size_t)b * (NN + 1)) * CC + tid;
        g_Pva[base] = 0.f; g_Pv[base] = 0.f; g_Pve[base] = 0.f;
    }

    // scalar streams: full-resolution Pa, Pe (fp64)
    int r0 = tid * 16;
    const float* s = &g_s[b * NN];
    const float* e = &g_e[b * NN];
    double l0 = 0.0, l1 = 0.0;
    for (int u = 0; u < 16; u++) {
        l0 += (double)s[r0 + u];
        l1 += (double)e[r0 + u];
    }
    sh0[tid] = l0; sh1[tid] = l1;
    __syncthreads();
    for (int off = 1; off < 256; off <<= 1) {
        double t0 = 0, t1 = 0;
        if (tid >= off) { t0 = sh0[tid - off]; t1 = sh1[tid - off]; }
        __syncthreads();
        sh0[tid] += t0; sh1[tid] += t1;
        __syncthreads();
    }
    double b0 = 0, b1 = 0;
    if (tid > 0) { b0 = sh0[tid - 1]; b1 = sh1[tid - 1]; }
    size_t base = (size_t)b * (NN + 1);
    if (tid == 0) { g_Pa[base] = 0.0; g_Pe[base] = 0.0; }
    double r0d = b0, r1d = b1;
    for (int u = 0; u < 16; u++) {
        int r = r0 + u;
        r0d += (double)s[r];
        r1d += (double)e[r];
        g_Pa[base + r + 1] = r0d;
        g_Pe[base + r + 1] = r1d;
    }
}

// ---------------- K4c: write full channel prefixes (fp32) -----------------
// grid = B*NT, block 256 = (c fast, q slow). Coalesced loads AND stores.
__global__ void k4c_scan() {
    __shared__ float pred[3 * 4 * CC];
    int blk = blockIdx.x;
    int b = blk / NT, tile = blk % NT;
    int tid = threadIdx.x;
    int c = tid & 63, q = tid >> 6;
    int rbase = tile * TILE + q * 32;

    const float* vs = &g_vs[((size_t)b * NN) * CC];
    const float* s  = &g_s[b * NN];
    const float* e  = &g_e[b * NN];

    // pass 1: own partial sums (for intra-tile q-offsets)
    float s0 = 0.f, s1 = 0.f, s2 = 0.f;
#pragma unroll 4
    for (int k = 0; k < 32; k++) {
        int r = rbase + k;
        float f = vs[(size_t)r * CC + c];
        s0 += f * s[r];
        s1 += f;
        s2 += f * e[r];
    }
    pred[(0 * 4 + q) * CC + c] = s0;
    pred[(1 * 4 + q) * CC + c] = s1;
    pred[(2 * 4 + q) * CC + c] = s2;
    __syncthreads();

    size_t toff = ((size_t)(b * NT + tile) * CC + c) * 3;
    float r0d = (float)g_tsum[toff + 0];
    float r1d = (float)g_tsum[toff + 1];
    float r2d = (float)g_tsum[toff + 2];
#pragma unroll
    for (int qq = 0; qq < 3; qq++) {
        if (qq < q) {
            r0d += pred[(0 * 4 + qq) * CC + c];
            r1d += pred[(1 * 4 + qq) * CC + c];
            r2d += pred[(2 * 4 + qq) * CC + c];
        }
    }

    // pass 2: sequential scan, coalesced stores (lanes over c, same r)
    size_t pbase = ((size_t)b * (NN + 1)) * CC + c;
    for (int k = 0; k < 32; k++) {
        int r = rbase + k;
        float f = vs[(size_t)r * CC + c];
        r0d += f * s[r];
        r1d += f;
        r2d += f * e[r];
        size_t o = pbase + (size_t)(r + 1) * CC;
        g_Pva[o] = r0d;
        g_Pv[o]  = r1d;
        g_Pve[o] = r2d;
    }
}

// ---------------- K5: per-column output -----------------------------------
// grid = BB*128 (32 j-columns per block), block 256.
// Stage the 3 prefix rows for the block's 32 columns through smem with
// coalesced row gathers; conflict-free (stride-65) smem reads; coalesced stores.
__global__ void __launch_bounds__(256) k5_out(const float* __restrict__ bg, float* __restrict__ out) {
    __shared__ float sh_s[NN];                       // 16KB
    __shared__ float sPva[32][65], sPv[32][65], sPve[32][65];  // ~25KB
    __shared__ float sh_tva[CC], sh_tv[CC], sh_bg[CC];
    __shared__ float sh_inv[32], sh_dj[32], sh_ed[32];
    __shared__ int sh_r[32];
    int blk = blockIdx.x;
    int b = blk >> 7;              // /128
    int jbase = (blk & 127) * 32;
    int tid = threadIdx.x;  // 256

    for (int e = tid; e < NN; e += 256) sh_s[e] = g_s[b * NN + e];
    if (tid < CC) {
        size_t totrow = ((size_t)b * (NN + 1) + NN) * CC;
        sh_tva[tid] = g_Pva[totrow + tid];
        sh_tv[tid]  = g_Pv[totrow + tid];
        sh_bg[tid]  = bg[tid];
    }
    __syncthreads();

    if (tid < 32) {
        int j = jbase + tid;
        double djd = g_dd[b * NN + j];
        float t = (float)(-djd);
        int lo = 0, hi = NN;
        while (lo < hi) {
            int mid = (lo + hi) >> 1;
            if (sh_s[mid] <= t) lo = mid + 1; else hi = mid;
        }
        int r = lo;
        double edd = exp(djd);
        size_t sbase = (size_t)b * (NN + 1);
        double SaN = g_Pa[sbase + NN];
        double S = (SaN - g_Pa[sbase + r]) + (double)(NN - r) * djd
                 + edd * g_Pe[sbase + r] - (double)r;
        sh_inv[tid] = (float)(1.0 / (1.5 * S));
        sh_dj[tid] = (float)djd;
        sh_ed[tid] = (float)edd;
        sh_r[tid] = r;
    }
    __syncthreads();

    // gather 32 prefix rows x 3 arrays, coalesced over c
    for (int e = tid; e < 32 * CC; e += 256) {
        int row = e >> 6, col = e & 63;
        size_t ro = ((size_t)b * (NN + 1) + sh_r[row]) * CC + col;
        sPva[row][col] = g_Pva[ro];
        sPv[row][col]  = g_Pv[ro];
        sPve[row][col] = g_Pve[ro];
    }
    __syncthreads();

    int j = tid & 31;          // lanes over j -> coalesced stores
    int cg = tid >> 5;         // 8 channel groups of 8
    float dj = sh_dj[j], ed = sh_ed[j], inv = sh_inv[j];
    float* ob = out + (size_t)b * CC * NN + jbase + j;
#pragma unroll
    for (int u = 0; u < 8; u++) {
        int c = cg * 8 + u;
        float pva = sPva[j][c];
        float pv  = sPv[j][c];
        float pve = sPve[j][c];
        float num = (sh_tva[c] - pva) + dj * (sh_tv[c] - pv) + ed * pve - pv;
        ob[(size_t)c * NN] = inv * num + sh_bg[c];
    }
}

// ---------------- launcher ----------------------------------------------
extern "C" void kernel_launch(void* const* d_in, const int* in_sizes, int n_in,
                              void* d_out, int out_size) {
    const float* x   = (const float*)d_in[0];
    const float* Wq  = (const float*)d_in[1];
    const float* bq  = (const float*)d_in[2];
    const float* Wk  = (const float*)d_in[3];
    const float* bk  = (const float*)d_in[4];
    const float* wcq = (const float*)d_in[5];
    const float* wck = (const float*)d_in[6];
    const float* Wv  = (const float*)d_in[7];
    const float* bv  = (const float*)d_in[8];
    const float* Wg  = (const float*)d_in[9];
    const float* bg  = (const float*)d_in[10];
    float* out = (float*)d_out;

    k1_precompute<<<1, 256>>>(Wq, bq, Wk, bk, wcq, wck, Wv, bv, Wg);
    k2_proj<<<(BB * NN) / 128, 128>>>(x);
    k3_sort<<<BB, 512>>>();
    k3p_permute<<<BB * 16, 256>>>();
    k4a_tilesum<<<BB * NT, 256>>>();
    k4b_offsets<<<BB, 256>>>();
    k4c_scan<<<BB * NT, 256>>>();
    k5_out<<<BB * 128, 256>>>(bg, out);
}

// round 7
// speedup vs baseline: 1.9754x; 1.0454x over previous
#include <cuda_runtime.h>
#include <math.h>
#include <cub/cub.cuh>

#define BB 4
#define CC 64
#define NN 4096
#define INTER 16
#define TILE 128
#define NT (NN / TILE)   // 32

// ---------------- scratch (device globals; no allocations allowed) ----------
__device__ double g_wa[CC], g_wd[CC];
__device__ double g_ca, g_cd;
__device__ __align__(16) float g_WvgT[CC * CC];   // [cin][o]
__device__ float g_bvg[CC];
__device__ float g_a[BB * NN];
__device__ double g_dd[BB * NN];                    // double-precision d
__device__ __align__(16) float g_vp[BB * NN * CC];  // [b][n][c]
__device__ float g_s[BB * NN];                       // sorted a (ascending)
__device__ float g_e[BB * NN];                       // expf(sorted a)
__device__ int   g_idx[BB * NN];                     // permutation
__device__ double g_tsum[BB * NT * CC * 3];          // tile sums -> exclusive offsets (fp64)
__device__ __align__(16) float g_Pva[BB * (NN + 1) * CC];  // prefix of v*a, [b][r][c]
__device__ __align__(16) float g_Pv [BB * (NN + 1) * CC];  // prefix of v
__device__ __align__(16) float g_Pve[BB * (NN + 1) * CC];  // prefix of v*exp(a)
__device__ double g_Pa[BB * (NN + 1)];               // prefix of a (double)
__device__ double g_Pe[BB * (NN + 1)];               // prefix of exp(a) (double)

// ---------------- K1: fold weights (double for the a/d path) -------------
__global__ void k1_precompute(const float* __restrict__ Wq, const float* __restrict__ bq,
                              const float* __restrict__ Wk, const float* __restrict__ bk,
                              const float* __restrict__ wcq, const float* __restrict__ wck,
                              const float* __restrict__ Wv, const float* __restrict__ bv,
                              const float* __restrict__ Wg) {
    int t = threadIdx.x;  // 256
    if (t < CC) {
        double sa = 0.0, sd = 0.0;
        for (int i = 0; i < INTER; i++) {
            sa += (double)wcq[i] * (double)Wq[i * CC + t];
            sd += (double)wck[i] * (double)Wk[i * CC + t];
        }
        g_wa[t] = sa;
        g_wd[t] = sd;
    }
    if (t >= 64 && t < 128) {
        int o = t - 64;
        float s = 0.f;
        for (int m = 0; m < CC; m++) s += Wg[o * CC + m] * bv[m];
        g_bvg[o] = s;
    }
    if (t == 128) {
        double ca = 0.0, cd = 0.0;
        for (int i = 0; i < INTER; i++) {
            ca += (double)wcq[i] * (double)bq[i];
            cd += (double)wck[i] * (double)bk[i];
        }
        g_ca = ca;
        g_cd = cd;
    }
    for (int e = t; e < CC * CC; e += 256) {
        int cin = e / CC, o = e % CC;
        float s = 0.f;
        for (int m = 0; m < CC; m++) s += Wg[o * CC + m] * Wv[m * CC + cin];
        g_WvgT[cin * CC + o] = s;
    }
}

// ---------------- K2: per-pixel projections a, d, v' ---------------------
__global__ void k2_proj(const float* __restrict__ x) {
    __shared__ __align__(16) float shW[CC * CC];
    __shared__ double shwa[CC], shwd[CC];
    __shared__ float shb[CC];
    int tid = threadIdx.x;  // 128
    for (int e = tid; e < CC * CC; e += 128) shW[e] = g_WvgT[e];
    if (tid < CC) { shwa[tid] = g_wa[tid]; shwd[tid] = g_wd[tid]; shb[tid] = g_bvg[tid]; }
    __syncthreads();

    int g = blockIdx.x * 128 + tid;  // 0 .. B*N-1
    int b = g / NN, n = g % NN;
    const float* xb = x + (size_t)b * CC * NN + n;

    float acc[CC];
#pragma unroll
    for (int o = 0; o < CC; o++) acc[o] = shb[o];
    double aa = g_ca, dd = g_cd;

    for (int cin = 0; cin < CC; cin++) {
        float xv = xb[(size_t)cin * NN];
        aa += shwa[cin] * (double)xv;
        dd += shwd[cin] * (double)xv;
        const float4* wrow = (const float4*)&shW[cin * CC];
#pragma unroll
        for (int o4 = 0; o4 < CC / 4; o4++) {
            float4 w = wrow[o4];
            acc[o4 * 4 + 0] += w.x * xv;
            acc[o4 * 4 + 1] += w.y * xv;
            acc[o4 * 4 + 2] += w.z * xv;
            acc[o4 * 4 + 3] += w.w * xv;
        }
    }
    g_a[g] = (float)aa;
    g_dd[g] = dd;
    float4* vout = (float4*)&g_vp[(size_t)g * CC];
#pragma unroll
    for (int o4 = 0; o4 < CC / 4; o4++)
        vout[o4] = make_float4(acc[o4 * 4 + 0], acc[o4 * 4 + 1], acc[o4 * 4 + 2], acc[o4 * 4 + 3]);
}

// ---------------- K3: per-batch radix sort of (a, idx); exp in epilogue ---
__global__ void __launch_bounds__(512) k3_sort() {
    typedef cub::BlockRadixSort<float, 512, 8, int> Sorter;
    __shared__ typename Sorter::TempStorage tmp;
    int b = blockIdx.x;
    int tid = threadIdx.x;  // 512

    float keys[8];
    int vals[8];
#pragma unroll
    for (int u = 0; u < 8; u++) {
        int r = 8 * tid + u;
        keys[u] = g_a[b * NN + r];
        vals[u] = r;
    }
    Sorter(tmp).Sort(keys, vals);  // ascending, blocked output
#pragma unroll
    for (int u = 0; u < 8; u++) {
        int r = 8 * tid + u;
        g_s[b * NN + r]   = keys[u];
        g_idx[b * NN + r] = vals[u];
        g_e[b * NN + r]   = expf(keys[u]);
    }
}

// ---------------- K4a: per-tile channel partial sums (fp32, inline gather)
// grid = B*NT, block 256 = (c fast 64, q slow 4). Each (c,q) sums 32 ranks.
__global__ void k4a_tilesum() {
    __shared__ float sred[3 * 4 * CC];
    int blk = blockIdx.x;
    int b = blk / NT, tile = blk % NT;
    int tid = threadIdx.x;
    int c = tid & 63, q = tid >> 6;
    int rbase = tile * TILE + q * 32;

    const float* vp  = &g_vp[((size_t)b * NN) * CC];
    const int*   idx = &g_idx[b * NN];
    const float* s   = &g_s[b * NN];
    const float* e   = &g_e[b * NN];

    float s0 = 0.f, s1 = 0.f, s2 = 0.f;
#pragma unroll 4
    for (int k = 0; k < 32; k++) {
        int r = rbase + k;
        int src = idx[r];                         // uniform over c-lanes
        float f = vp[(size_t)src * CC + c];       // coalesced row gather
        s0 += f * s[r];
        s1 += f;
        s2 += f * e[r];
    }
    sred[(0 * 4 + q) * CC + c] = s0;
    sred[(1 * 4 + q) * CC + c] = s1;
    sred[(2 * 4 + q) * CC + c] = s2;
    __syncthreads();
    if (tid < CC) {
        size_t out = ((size_t)(b * NT + tile) * CC + tid) * 3;
        for (int st = 0; st < 3; st++) {
            float t = sred[(st * 4 + 0) * CC + tid] + sred[(st * 4 + 1) * CC + tid]
                    + sred[(st * 4 + 2) * CC + tid] + sred[(st * 4 + 3) * CC + tid];
            g_tsum[out + st] = (double)t;
        }
    }
}

// ---------------- K4b: tile-sum exclusive scan (fp64) + scalar Pa/Pe ------
// grid = B, block 256.
__global__ void k4b_offsets() {
    __shared__ double sh0[256], sh1[256];
    int b = blockIdx.x;
    int tid = threadIdx.x;

    if (tid < CC) {
        double run0 = 0.0, run1 = 0.0, run2 = 0.0;
        for (int t = 0; t < NT; t++) {
            size_t o = ((size_t)(b * NT + t) * CC + tid) * 3;
            double v0 = g_tsum[o + 0], v1 = g_tsum[o + 1], v2 = g_tsum[o + 2];
            g_tsum[o + 0] = run0; g_tsum[o + 1] = run1; g_tsum[o + 2] = run2;
            run0 += v0; run1 += v1; run2 += v2;
        }
        size_t base = ((size_t)b * (NN + 1)) * CC + tid;
        g_Pva[base] = 0.f; g_Pv[base] = 0.f; g_Pve[base] = 0.f;
    }

    // scalar streams: full-resolution Pa, Pe (fp64)
    int r0 = tid * 16;
    const float* s = &g_s[b * NN];
    const float* e = &g_e[b * NN];
    double l0 = 0.0, l1 = 0.0;
    for (int u = 0; u < 16; u++) {
        l0 += (double)s[r0 + u];
        l1 += (double)e[r0 + u];
    }
    sh0[tid] = l0; sh1[tid] = l1;
    __syncthreads();
    for (int off = 1; off < 256; off <<= 1) {
        double t0 = 0, t1 = 0;
        if (tid >= off) { t0 = sh0[tid - off]; t1 = sh1[tid - off]; }
        __syncthreads();
        sh0[tid] += t0; sh1[tid] += t1;
        __syncthreads();
    }
    double b0 = 0, b1 = 0;
    if (tid > 0) { b0 = sh0[tid - 1]; b1 = sh1[tid - 1]; }
    size_t base = (size_t)b * (NN + 1);
    if (tid == 0) { g_Pa[base] = 0.0; g_Pe[base] = 0.0; }
    double r0d = b0, r1d = b1;
    for (int u = 0; u < 16; u++) {
        int r = r0 + u;
        r0d += (double)s[r];
        r1d += (double)e[r];
        g_Pa[base + r + 1] = r0d;
        g_Pe[base + r + 1] = r1d;
    }
}

// ---------------- K4c: write full channel prefixes (fp32, inline gather) --
// grid = B*NT, block 256 = (c fast, q slow). Coalesced gather AND stores.
__global__ void k4c_scan() {
    __shared__ float pred[3 * 4 * CC];
    int blk = blockIdx.x;
    int b = blk / NT, tile = blk % NT;
    int tid = threadIdx.x;
    int c = tid & 63, q = tid >> 6;
    int rbase = tile * TILE + q * 32;

    const float* vp  = &g_vp[((size_t)b * NN) * CC];
    const int*   idx = &g_idx[b * NN];
    const float* s   = &g_s[b * NN];
    const float* e   = &g_e[b * NN];

    // pass 1: own partial sums (for intra-tile q-offsets); keep f in regs
    float fv[32];
    float s0 = 0.f, s1 = 0.f, s2 = 0.f;
#pragma unroll 4
    for (int k = 0; k < 32; k++) {
        int r = rbase + k;
        int src = idx[r];
        float f = vp[(size_t)src * CC + c];
        fv[k] = f;
        s0 += f * s[r];
        s1 += f;
        s2 += f * e[r];
    }
    pred[(0 * 4 + q) * CC + c] = s0;
    pred[(1 * 4 + q) * CC + c] = s1;
    pred[(2 * 4 + q) * CC + c] = s2;
    __syncthreads();

    size_t toff = ((size_t)(b * NT + tile) * CC + c) * 3;
    float r0d = (float)g_tsum[toff + 0];
    float r1d = (float)g_tsum[toff + 1];
    float r2d = (float)g_tsum[toff + 2];
#pragma unroll
    for (int qq = 0; qq < 3; qq++) {
        if (qq < q) {
            r0d += pred[(0 * 4 + qq) * CC + c];
            r1d += pred[(1 * 4 + qq) * CC + c];
            r2d += pred[(2 * 4 + qq) * CC + c];
        }
    }

    // pass 2: sequential scan from registers, coalesced stores
    size_t pbase = ((size_t)b * (NN + 1)) * CC + c;
#pragma unroll 4
    for (int k = 0; k < 32; k++) {
        int r = rbase + k;
        float f = fv[k];
        r0d += f * s[r];
        r1d += f;
        r2d += f * e[r];
        size_t o = pbase + (size_t)(r + 1) * CC;
        g_Pva[o] = r0d;
        g_Pv[o]  = r1d;
        g_Pve[o] = r2d;
    }
}

// ---------------- K5: per-column output -----------------------------------
// grid = BB*128 (32 j-columns per block), block 256.
__global__ void __launch_bounds__(256) k5_out(const float* __restrict__ bg, float* __restrict__ out) {
    __shared__ float sPva[32][65], sPv[32][65], sPve[32][65];  // ~25KB
    __shared__ float sh_tva[CC], sh_tv[CC], sh_bg[CC];
    __shared__ float sh_inv[32], sh_dj[32], sh_ed[32];
    __shared__ int sh_r[32];
    int blk = blockIdx.x;
    int b = blk >> 7;              // /128
    int jbase = (blk & 127) * 32;
    int tid = threadIdx.x;  // 256

    if (tid < CC) {
        size_t totrow = ((size_t)b * (NN + 1) + NN) * CC;
        sh_tva[tid] = g_Pva[totrow + tid];
        sh_tv[tid]  = g_Pv[totrow + tid];
        sh_bg[tid]  = bg[tid];
    }

    if (tid < 32) {
        int j = jbase + tid;
        double djd = g_dd[b * NN + j];
        float t = (float)(-djd);
        const float* s = &g_s[b * NN];
        int lo = 0, hi = NN;
        while (lo < hi) {
            int mid = (lo + hi) >> 1;
            if (s[mid] <= t) lo = mid + 1; else hi = mid;
        }
        int r = lo;
        double edd = exp(djd);
        size_t sbase = (size_t)b * (NN + 1);
        double SaN = g_Pa[sbase + NN];
        double S = (SaN - g_Pa[sbase + r]) + (double)(NN - r) * djd
                 + edd * g_Pe[sbase + r] - (double)r;
        sh_inv[tid] = (float)(1.0 / (1.5 * S));
        sh_dj[tid] = (float)djd;
        sh_ed[tid] = (float)edd;
        sh_r[tid] = r;
    }
    __syncthreads();

    // gather 32 prefix rows x 3 arrays, coalesced over c
    for (int e = tid; e < 32 * CC; e += 256) {
        int row = e >> 6, col = e & 63;
        size_t ro = ((size_t)b * (NN + 1) + sh_r[row]) * CC + col;
        sPva[row][col] = g_Pva[ro];
        sPv[row][col]  = g_Pv[ro];
        sPve[row][col] = g_Pve[ro];
    }
    __syncthreads();

    int j = tid & 31;          // lanes over j -> coalesced stores
    int cg = tid >> 5;         // 8 channel groups of 8
    float dj = sh_dj[j], ed = sh_ed[j], inv = sh_inv[j];
    float* ob = out + (size_t)b * CC * NN + jbase + j;
#pragma unroll
    for (int u = 0; u < 8; u++) {
        int c = cg * 8 + u;
        float pva = sPva[j][c];
        float pv  = sPv[j][c];
        float pve = sPve[j][c];
        float num = (sh_tva[c] - pva) + dj * (sh_tv[c] - pv) + ed * pve - pv;
        ob[(size_t)c * NN] = inv * num + sh_bg[c];
    }
}

// ---------------- launcher ----------------------------------------------
extern "C" void kernel_launch(void* const* d_in, const int* in_sizes, int n_in,
                              void* d_out, int out_size) {
    const float* x   = (const float*)d_in[0];
    const float* Wq  = (const float*)d_in[1];
    const float* bq  = (const float*)d_in[2];
    const float* Wk  = (const float*)d_in[3];
    const float* bk  = (const float*)d_in[4];
    const float* wcq = (const float*)d_in[5];
    const float* wck = (const float*)d_in[6];
    const float* Wv  = (const float*)d_in[7];
    const float* bv  = (const float*)d_in[8];
    const float* Wg  = (const float*)d_in[9];
    const float* bg  = (const float*)d_in[10];
    float* out = (float*)d_out;

    k1_precompute<<<1, 256>>>(Wq, bq, Wk, bk, wcq, wck, Wv, bv, Wg);
    k2_proj<<<(BB * NN) / 128, 128>>>(x);
    k3_sort<<<BB, 512>>>();
    k4a_tilesum<<<BB * NT, 256>>>();
    k4b_offsets<<<BB, 256>>>();
    k4c_scan<<<BB * NT, 256>>>();
    k5_out<<<BB * 128, 256>>>(bg, out);
}

// round 9
// speedup vs baseline: 2.2785x; 1.1535x over previous
#include <cuda_runtime.h>
#include <math.h>
#include <cub/cub.cuh>

#define BB 4
#define CC 64
#define NN 4096
#define INTER 16
#define TILE 128
#define NT (NN / TILE)   // 32

// ---------------- scratch (device globals; no allocations allowed) ----------
__device__ float g_a[BB * NN];
__device__ double g_dd[BB * NN];                    // double-precision d
__device__ __align__(16) float g_vp[BB * NN * CC];  // [b][n][c]
__device__ float g_s[BB * NN];                       // sorted a (ascending)
__device__ float g_e[BB * NN];                       // expf(sorted a)
__device__ int   g_idx[BB * NN];                     // permutation
__device__ __align__(16) float g_Pva[BB * (NN + 1) * CC];  // prefix of v*a, [b][r][c]
__device__ __align__(16) float g_Pv [BB * (NN + 1) * CC];  // prefix of v
__device__ __align__(16) float g_Pve[BB * (NN + 1) * CC];  // prefix of v*exp(a)
__device__ double g_Pa[BB * (NN + 1)];               // prefix of a (double)
__device__ double g_Pe[BB * (NN + 1)];               // prefix of exp(a) (double)
// decoupled-lookback state: 0=invalid, 1=aggregate ready, 2=prefix ready
__device__ int   g_state[BB * NT];
__device__ float g_agg [BB * NT * 3 * CC];           // [blk][stream][c]
__device__ float g_pref[BB * NT * 3 * CC];           // inclusive prefix

// ---------------- K2: fold weights + per-pixel projections a, d, v' -------
__global__ void __launch_bounds__(128) k2_proj(
        const float* __restrict__ x,
        const float* __restrict__ Wq, const float* __restrict__ bq,
        const float* __restrict__ Wk, const float* __restrict__ bk,
        const float* __restrict__ wcq, const float* __restrict__ wck,
        const float* __restrict__ Wv, const float* __restrict__ bv,
        const float* __restrict__ Wg) {
    __shared__ __align__(16) float shW[CC * CC];
    __shared__ double shwa[CC], shwd[CC];
    __shared__ float shb[CC];
    __shared__ double shca, shcd;
    int tid = threadIdx.x;  // 128

    // ---- fold weights in-block (identical math to old k1) ----
    for (int e = tid; e < CC * CC; e += 128) {
        int cin = e / CC, o = e % CC;
        float s = 0.f;
        for (int m = 0; m < CC; m++) s += Wg[o * CC + m] * Wv[m * CC + cin];
        shW[cin * CC + o] = s;
    }
    if (tid < CC) {
        double sa = 0.0, sd = 0.0;
        for (int i = 0; i < INTER; i++) {
            sa += (double)wcq[i] * (double)Wq[i * CC + tid];
            sd += (double)wck[i] * (double)Wk[i * CC + tid];
        }
        shwa[tid] = sa;
        shwd[tid] = sd;
        float s = 0.f;
        for (int m = 0; m < CC; m++) s += Wg[tid * CC + m] * bv[m];
        shb[tid] = s;
    }
    if (tid == 0) {
        double ca = 0.0, cd = 0.0;
        for (int i = 0; i < INTER; i++) {
            ca += (double)wcq[i] * (double)bq[i];
            cd += (double)wck[i] * (double)bk[i];
        }
        shca = ca;
        shcd = cd;
    }
    __syncthreads();

    int g = blockIdx.x * 128 + tid;  // 0 .. B*N-1
    int b = g / NN, n = g % NN;
    const float* xb = x + (size_t)b * CC * NN + n;

    float acc[CC];
#pragma unroll
    for (int o = 0; o < CC; o++) acc[o] = shb[o];
    double aa = shca, dd = shcd;

    for (int cin = 0; cin < CC; cin++) {
        float xv = xb[(size_t)cin * NN];
        aa += shwa[cin] * (double)xv;
        dd += shwd[cin] * (double)xv;
        const float4* wrow = (const float4*)&shW[cin * CC];
#pragma unroll
        for (int o4 = 0; o4 < CC / 4; o4++) {
            float4 w = wrow[o4];
            acc[o4 * 4 + 0] += w.x * xv;
            acc[o4 * 4 + 1] += w.y * xv;
            acc[o4 * 4 + 2] += w.z * xv;
            acc[o4 * 4 + 3] += w.w * xv;
        }
    }
    g_a[g] = (float)aa;
    g_dd[g] = dd;
    float4* vout = (float4*)&g_vp[(size_t)g * CC];
#pragma unroll
    for (int o4 = 0; o4 < CC / 4; o4++)
        vout[o4] = make_float4(acc[o4 * 4 + 0], acc[o4 * 4 + 1], acc[o4 * 4 + 2], acc[o4 * 4 + 3]);
}

// ---------------- K3: sort + exp + fp64 Pa/Pe scan + state init -----------
__global__ void __launch_bounds__(512) k3_sort() {
    typedef cub::BlockRadixSort<float, 512, 8, int> Sorter;
    __shared__ union U {
        typename Sorter::TempStorage sort;
        double red[2 * 512];
        __device__ U() {}
    } tmp;
    int b = blockIdx.x;
    int tid = threadIdx.x;  // 512

    float keys[8];
    int vals[8];
#pragma unroll
    for (int u = 0; u < 8; u++) {
        int r = 8 * tid + u;
        keys[u] = g_a[b * NN + r];
        vals[u] = r;
    }
    Sorter(tmp.sort).Sort(keys, vals);  // ascending, blocked output

    float ev[8];
    double l0 = 0.0, l1 = 0.0;
#pragma unroll
    for (int u = 0; u < 8; u++) {
        int r = 8 * tid + u;
        ev[u] = expf(keys[u]);
        g_s[b * NN + r]   = keys[u];
        g_idx[b * NN + r] = vals[u];
        g_e[b * NN + r]   = ev[u];
        l0 += (double)keys[u];
        l1 += (double)ev[u];
    }
    __syncthreads();  // smem reuse barrier

    // Hillis-Steele inclusive scan of per-thread sums (fp64, 2 streams)
    tmp.red[tid] = l0;
    tmp.red[512 + tid] = l1;
    __syncthreads();
    for (int off = 1; off < 512; off <<= 1) {
        double t0 = 0, t1 = 0;
        if (tid >= off) { t0 = tmp.red[tid - off]; t1 = tmp.red[512 + tid - off]; }
        __syncthreads();
        tmp.red[tid] += t0;
        tmp.red[512 + tid] += t1;
        __syncthreads();
    }
    double b0 = 0, b1 = 0;
    if (tid > 0) { b0 = tmp.red[tid - 1]; b1 = tmp.red[512 + tid - 1]; }

    size_t base = (size_t)b * (NN + 1);
    if (tid == 0) { g_Pa[base] = 0.0; g_Pe[base] = 0.0; }
    double r0d = b0, r1d = b1;
#pragma unroll
    for (int u = 0; u < 8; u++) {
        int r = 8 * tid + u;
        r0d += (double)keys[u];
        r1d += (double)ev[u];
        g_Pa[base + r + 1] = r0d;
        g_Pe[base + r + 1] = r1d;
    }

    // zero prefix row 0 and lookback states for this batch
    if (tid < CC) {
        size_t p0 = ((size_t)b * (NN + 1)) * CC + tid;
        g_Pva[p0] = 0.f; g_Pv[p0] = 0.f; g_Pve[p0] = 0.f;
    }
    if (tid < NT) g_state[b * NT + tid] = 0;
}

// ---------------- K4: single-pass channel prefix scan (decoupled lookback)
// grid = B*NT (<=148: whole grid co-resident -> deadlock-free), block 256.
__global__ void __launch_bounds__(256) k4_scan() {
    __shared__ float s_s[TILE], s_e[TILE];
    __shared__ int s_idx[TILE];
    __shared__ float partial[3][4][CC];
    __shared__ float s_off[3][CC];
    int blk = blockIdx.x;
    int b = blk / NT, tile = blk % NT;
    int tid = threadIdx.x;
    int c = tid & 63, q = tid >> 6;
    int rloc = q * 32;                     // local rank base within tile
    int rglob = tile * TILE;

    // stage tile's sorted keys / exps / idx
    for (int i = tid; i < TILE; i += 256) {
        s_s[i]   = g_s[b * NN + rglob + i];
        s_e[i]   = g_e[b * NN + rglob + i];
        s_idx[i] = g_idx[b * NN + rglob + i];
    }
    __syncthreads();

    // gather all 32 rows (high MLP), compute local partial sums
    const float* vp = &g_vp[((size_t)b * NN) * CC];
    float fv[32];
#pragma unroll
    for (int k = 0; k < 32; k++)
        fv[k] = vp[(size_t)s_idx[rloc + k] * CC + c];
    float s0 = 0.f, s1 = 0.f, s2 = 0.f;
#pragma unroll
    for (int k = 0; k < 32; k++) {
        float f = fv[k];
        s0 += f * s_s[rloc + k];
        s1 += f;
        s2 += f * s_e[rloc + k];
    }
    partial[0][q][c] = s0;
    partial[1][q][c] = s1;
    partial[2][q][c] = s2;
    __syncthreads();

    // per-channel tile aggregate; publish
    float a0 = 0.f, a1 = 0.f, a2 = 0.f;
    if (tid < CC) {
        a0 = partial[0][0][tid] + partial[0][1][tid] + partial[0][2][tid] + partial[0][3][tid];
        a1 = partial[1][0][tid] + partial[1][1][tid] + partial[1][2][tid] + partial[1][3][tid];
        a2 = partial[2][0][tid] + partial[2][1][tid] + partial[2][2][tid] + partial[2][3][tid];
        size_t ob = (size_t)blk * 3 * CC + tid;
        if (tile == 0) {
            g_pref[ob + 0 * CC] = a0;
            g_pref[ob + 1 * CC] = a1;
            g_pref[ob + 2 * CC] = a2;
        } else {
            g_agg[ob + 0 * CC] = a0;
            g_agg[ob + 1 * CC] = a1;
            g_agg[ob + 2 * CC] = a2;
        }
    }
    __syncthreads();
    __threadfence();
    if (tid == 0) *((volatile int*)&g_state[blk]) = (tile == 0) ? 2 : 1;

    // lookback: fp64 accumulation of fp32 aggregates (matches old tsum scan)
    double o0 = 0.0, o1 = 0.0, o2 = 0.0;
    if (tile > 0 && tid < CC) {
        volatile float* vagg  = (volatile float*)g_agg;
        volatile float* vpref = (volatile float*)g_pref;
        int p = blk - 1;
        while (true) {
            int st;
            do { st = *((volatile int*)&g_state[p]); } while (st == 0);
            size_t pb = (size_t)p * 3 * CC + tid;
            if (st == 2) {
                o0 += (double)vpref[pb + 0 * CC];
                o1 += (double)vpref[pb + 1 * CC];
                o2 += (double)vpref[pb + 2 * CC];
                break;
            } else {
                o0 += (double)vagg[pb + 0 * CC];
                o1 += (double)vagg[pb + 1 * CC];
                o2 += (double)vagg[pb + 2 * CC];
                p--;
            }
        }
        // publish own inclusive prefix
        size_t ob = (size_t)blk * 3 * CC + tid;
        g_pref[ob + 0 * CC] = (float)(o0 + (double)a0);
        g_pref[ob + 1 * CC] = (float)(o1 + (double)a1);
        g_pref[ob + 2 * CC] = (float)(o2 + (double)a2);
    }
    if (tile > 0) {
        __syncthreads();
        __threadfence();
        if (tid == 0) *((volatile int*)&g_state[blk]) = 2;
    }
    if (tid < CC) {
        s_off[0][tid] = (float)o0;
        s_off[1][tid] = (float)o1;
        s_off[2][tid] = (float)o2;
    }
    __syncthreads();

    // intra-tile exclusive base for this (c,q)
    float r0 = s_off[0][c], r1 = s_off[1][c], r2 = s_off[2][c];
#pragma unroll
    for (int qq = 0; qq < 3; qq++) {
        if (qq < q) {
            r0 += partial[0][qq][c];
            r1 += partial[1][qq][c];
            r2 += partial[2][qq][c];
        }
    }

    // sequential scan from registers, coalesced stores over c
    size_t pbase = ((size_t)b * (NN + 1)) * CC + c;
#pragma unroll 4
    for (int k = 0; k < 32; k++) {
        float f = fv[k];
        r0 += f * s_s[rloc + k];
        r1 += f;
        r2 += f * s_e[rloc + k];
        size_t o = pbase + (size_t)(rglob + rloc + k + 1) * CC;
        g_Pva[o] = r0;
        g_Pv[o]  = r1;
        g_Pve[o] = r2;
    }
}

// ---------------- K5: per-column output -----------------------------------
// grid = BB*128 (32 j-columns per block), block 256.
__global__ void __launch_bounds__(256) k5_out(const float* __restrict__ bg, float* __restrict__ out) {
    __shared__ float sPva[32][65], sPv[32][65], sPve[32][65];  // ~25KB
    __shared__ float sh_tva[CC], sh_tv[CC], sh_bg[CC];
    __shared__ float sh_inv[32], sh_dj[32], sh_ed[32];
    __shared__ int sh_r[32];
    int blk = blockIdx.x;
    int b = blk >> 7;              // /128
    int jbase = (blk & 127) * 32;
    int tid = threadIdx.x;  // 256

    if (tid < CC) {
        size_t totrow = ((size_t)b * (NN + 1) + NN) * CC;
        sh_tva[tid] = g_Pva[totrow + tid];
        sh_tv[tid]  = g_Pv[totrow + tid];
        sh_bg[tid]  = bg[tid];
    }

    if (tid < 32) {
        int j = jbase + tid;
        double djd = g_dd[b * NN + j];
        float t = (float)(-djd);
        const float* s = &g_s[b * NN];
        int lo = 0, hi = NN;
        while (lo < hi) {
            int mid = (lo + hi) >> 1;
            if (s[mid] <= t) lo = mid + 1; else hi = mid;
        }
        int r = lo;
        double edd = exp(djd);
        size_t sbase = (size_t)b * (NN + 1);
        double SaN = g_Pa[sbase + NN];
        double S = (SaN - g_Pa[sbase + r]) + (double)(NN - r) * djd
                 + edd * g_Pe[sbase + r] - (double)r;
        sh_inv[tid] = (float)(1.0 / (1.5 * S));
        sh_dj[tid] = (float)djd;
        sh_ed[tid] = (float)edd;
        sh_r[tid] = r;
    }
    __syncthreads();

    // gather 32 prefix rows x 3 arrays, coalesced over c
    for (int e = tid; e < 32 * CC; e += 256) {
        int row = e >> 6, col = e & 63;
        size_t ro = ((size_t)b * (NN + 1) + sh_r[row]) * CC + col;
        sPva[row][col] = g_Pva[ro];
        sPv[row][col]  = g_Pv[ro];
        sPve[row][col] = g_Pve[ro];
    }
    __syncthreads();

    int j = tid & 31;          // lanes over j -> coalesced stores
    int cg = tid >> 5;         // 8 channel groups of 8
    float dj = sh_dj[j], ed = sh_ed[j], inv = sh_inv[j];
    float* ob = out + (size_t)b * CC * NN + jbase + j;
#pragma unroll
    for (int u = 0; u < 8; u++) {
        int c = cg * 8 + u;
        float pva = sPva[j][c];
        float pv  = sPv[j][c];
        float pve = sPve[j][c];
        float num = (sh_tva[c] - pva) + dj * (sh_tv[c] - pv) + ed * pve - pv;
        ob[(size_t)c * NN] = inv * num + sh_bg[c];
    }
}

// ---------------- launcher ----------------------------------------------
extern "C" void kernel_launch(void* const* d_in, const int* in_sizes, int n_in,
                              void* d_out, int out_size) {
    const float* x   = (const float*)d_in[0];
    const float* Wq  = (const float*)d_in[1];
    const float* bq  = (const float*)d_in[2];
    const float* Wk  = (const float*)d_in[3];
    const float* bk  = (const float*)d_in[4];
    const float* wcq = (const float*)d_in[5];
    const float* wck = (const float*)d_in[6];
    const float* Wv  = (const float*)d_in[7];
    const float* bv  = (const float*)d_in[8];
    const float* Wg  = (const float*)d_in[9];
    const float* bg  = (const float*)d_in[10];
    float* out = (float*)d_out;

    k2_proj<<<(BB * NN) / 128, 128>>>(x, Wq, bq, Wk, bk, wcq, wck, Wv, bv, Wg);
    k3_sort<<<BB, 512>>>();
    k4_scan<<<BB * NT, 256>>>();
    k5_out<<<BB * 128, 256>>>(bg, out);
}